// round 3
// baseline (speedup 1.0000x reference)
#include <cuda_runtime.h>

// Per-edge dot product: out[e] = dot(h[src[e]], h[dst[e]]), D=128 fp32.
// 8 lanes per "octet"; each octet handles TWO edges (2g, 2g+1).
// Lane `sub` loads float4 chunks sub, sub+8, sub+16, sub+24 of each 512B row:
// every warp-level LDG.128 touches exactly 4 full 128B lines, and each thread
// has up to 16 independent loads in flight.
// Index dtype (int32 vs int64) detected at runtime from the bit pattern.

__device__ int g_is_i32;

// If indices are int64 with values < 2^31, every odd int32 word is zero.
// Any nonzero odd word proves int32. Overwritten unconditionally each launch.
__global__ void detect_idx_dtype_kernel(const int* __restrict__ s) {
    __shared__ int red[256];
    int t = threadIdx.x;
    int nz = 0;
    #pragma unroll
    for (int i = t; i < 4096; i += 256) nz |= s[2 * i + 1];
    red[t] = nz;
    __syncthreads();
    #pragma unroll
    for (int off = 128; off > 0; off >>= 1) {
        if (t < off) red[t] |= red[t + off];
        __syncthreads();
    }
    if (t == 0) g_is_i32 = (red[0] != 0) ? 1 : 0;
}

__device__ __forceinline__ float dot4(float4 a, float4 b) {
    return fmaf(a.x, b.x, fmaf(a.y, b.y, fmaf(a.z, b.z, a.w * b.w)));
}

__global__ void __launch_bounds__(256, 4) edge_dot_kernel(
    const float* __restrict__ h,
    const void* __restrict__ srcp,
    const void* __restrict__ dstp,
    float* __restrict__ out,
    int n_edges)
{
    int tid = (int)(blockIdx.x * 256u + threadIdx.x);
    int oct = tid >> 3;            // octet id; handles edges 2*oct, 2*oct+1
    int sub = threadIdx.x & 7;
    int e0  = oct * 2;
    if (e0 >= n_edges) return;

    long long s0, d0, s1, d1;
    bool dual = (e0 + 1) < n_edges;

    if (g_is_i32) {
        if (dual) {
            int2 sv = ((const int2*)srcp)[oct];
            int2 dv = ((const int2*)dstp)[oct];
            s0 = sv.x; s1 = sv.y; d0 = dv.x; d1 = dv.y;
        } else {
            s0 = ((const int*)srcp)[e0];
            d0 = ((const int*)dstp)[e0];
            s1 = s0; d1 = d0;
        }
    } else {
        if (dual) {
            longlong2 sv = ((const longlong2*)srcp)[oct];
            longlong2 dv = ((const longlong2*)dstp)[oct];
            s0 = sv.x; s1 = sv.y; d0 = dv.x; d1 = dv.y;
        } else {
            s0 = ((const long long*)srcp)[e0];
            d0 = ((const long long*)dstp)[e0];
            s1 = s0; d1 = d0;
        }
    }

    const float4* __restrict__ a4 = (const float4*)(h + s0 * 128) + sub;
    const float4* __restrict__ b4 = (const float4*)(h + d0 * 128) + sub;
    const float4* __restrict__ c4 = (const float4*)(h + s1 * 128) + sub;
    const float4* __restrict__ e4 = (const float4*)(h + d1 * 128) + sub;

    // Edge 0: 8 independent 16B loads.
    float4 a0 = a4[0], a1 = a4[8], a2 = a4[16], a3 = a4[24];
    float4 b0 = b4[0], b1 = b4[8], b2 = b4[16], b3 = b4[24];
    // Edge 1: 8 more independent loads (compiler pipelines under edge-0 FMAs).
    float4 c0 = c4[0], c1 = c4[8], c2 = c4[16], c3 = c4[24];
    float4 f0 = e4[0], f1 = e4[8], f2 = e4[16], f3 = e4[24];

    float sum0 = (dot4(a0, b0) + dot4(a1, b1)) + (dot4(a2, b2) + dot4(a3, b3));
    float sum1 = (dot4(c0, f0) + dot4(c1, f1)) + (dot4(c2, f2) + dot4(c3, f3));

    // Interleaved butterflies over the 8-lane octet (hide SHFL latency).
    sum0 += __shfl_xor_sync(0xffffffffu, sum0, 4);
    sum1 += __shfl_xor_sync(0xffffffffu, sum1, 4);
    sum0 += __shfl_xor_sync(0xffffffffu, sum0, 2);
    sum1 += __shfl_xor_sync(0xffffffffu, sum1, 2);
    sum0 += __shfl_xor_sync(0xffffffffu, sum0, 1);
    sum1 += __shfl_xor_sync(0xffffffffu, sum1, 1);

    if (sub == 0) {
        if (dual) {
            ((float2*)out)[oct] = make_float2(sum0, sum1);   // 8B coalesced
        } else {
            out[e0] = sum0;
        }
    }
}

extern "C" void kernel_launch(void* const* d_in, const int* in_sizes, int n_in,
                              void* d_out, int out_size) {
    const float* h   = (const float*)d_in[0];
    const void*  src = d_in[1];
    const void*  dst = d_in[2];
    float* out = (float*)d_out;

    int n_edges = in_sizes[1];  // element count of src == E

    detect_idx_dtype_kernel<<<1, 256>>>((const int*)src);

    // 2 edges per octet, 32 octets per 256-thread block -> 64 edges per block
    int blocks = (n_edges + 63) / 64;
    edge_dot_kernel<<<blocks, 256>>>(h, src, dst, out, n_edges);
}